// round 16
// baseline (speedup 1.0000x reference)
#include <cuda_runtime.h>
#include <cuda_fp16.h>
#include <cstdint>
#include <math.h>

#define Tn   2048
#define Dm   1024
#define Ne   64
#define TOPK 8
#define Hh   256
#define ESn  2
#define HSn  2048
#define MAXP (Tn * TOPK)
#define MAXTILES 256

// ---------------- static scratch ----------------
__device__ float g_topw[MAXP];
__device__ int   g_topi[MAXP];
__device__ int   g_slot2pair[MAXP];
__device__ int   g_count[Ne];
__device__ int   g_offset[Ne];
__device__ int   g_cursor[Ne];
__device__ int   g_pair_token[MAXP];
__device__ float g_pair_w[MAXP];
__device__ int   g_ntiles;
__device__ int   g_tile_e[MAXTILES];
__device__ int   g_tile_row[MAXTILES];
__device__ int   g_ntiles64;
__device__ int   g_t64_e[Ne];
__device__ int   g_t64_row[Ne];
__device__ __half g_pairout16[(size_t)MAXP * Dm];
__device__ float  g_sharedsum[(size_t)Tn * Dm];
__device__ __half g_H16[(size_t)MAXP * Hh];
__device__ __half g_Hs16[(size_t)ESn * Tn * HSn];
// fp16 operand copies
__device__ __half g_x16[(size_t)Tn * Dm];
__device__ __half g_w116[(size_t)Ne * Dm * Hh];
__device__ __half g_w216[(size_t)Ne * Hh * Dm];
__device__ __half g_sw116[(size_t)ESn * Dm * HSn];
__device__ __half g_sw216[(size_t)ESn * HSn * Dm];

__device__ __forceinline__ uint32_t smem_u32(const void* p) {
    uint32_t a;
    asm("{ .reg .u64 t; cvta.to.shared.u64 t, %1; cvt.u32.u64 %0, t; }" : "=r"(a) : "l"(p));
    return a;
}
__device__ __forceinline__ float silu_f(float c) { return c / (1.0f + __expf(-c)); }

__device__ __forceinline__ void ldsm_x4(uint32_t* r, uint32_t addr) {
    asm volatile("ldmatrix.sync.aligned.m8n8.x4.shared.b16 {%0,%1,%2,%3}, [%4];"
        : "=r"(r[0]), "=r"(r[1]), "=r"(r[2]), "=r"(r[3]) : "r"(addr));
}
__device__ __forceinline__ void ldsm_x4_trans(uint32_t* r, uint32_t addr) {
    asm volatile("ldmatrix.sync.aligned.m8n8.x4.trans.shared.b16 {%0,%1,%2,%3}, [%4];"
        : "=r"(r[0]), "=r"(r[1]), "=r"(r[2]), "=r"(r[3]) : "r"(addr));
}
__device__ __forceinline__ void mma_fp16(float* d, const uint32_t* a, uint32_t b0, uint32_t b1) {
    asm volatile(
        "mma.sync.aligned.m16n8k16.row.col.f32.f16.f16.f32 "
        "{%0,%1,%2,%3}, {%4,%5,%6,%7}, {%8,%9}, {%0,%1,%2,%3};"
        : "+f"(d[0]), "+f"(d[1]), "+f"(d[2]), "+f"(d[3])
        : "r"(a[0]), "r"(a[1]), "r"(a[2]), "r"(a[3]), "r"(b0), "r"(b1));
}
__device__ __forceinline__ void cp16(uint32_t dst, const void* src, uint32_t sz) {
    asm volatile("cp.async.cg.shared.global [%0], [%1], 16, %2;"
        :: "r"(dst), "l"(src), "r"(sz) : "memory");
}
#define CP_COMMIT() asm volatile("cp.async.commit_group;" ::: "memory")
#define CP_WAIT(n)  asm volatile("cp.async.wait_group %0;" :: "n"(n) : "memory")

// pipeline geometry: K-chunk = 64 (stage sized for the M=128 variant; M=64 wastes A space, fine)
#define NSTAGE 3
#define PA_B 144
#define PB_B 272
#define STG_A 18432
#define STG_B 17408
#define STG_BYTES (STG_A + STG_B)
#define SMEM_DYN (1024 + NSTAGE * STG_BYTES)   // 108544

struct GemmArgs {
    const __half* A; int lda; const int* gather; int valid;
    const __half* W; int ldw; int n0;
    int K;
    const float* bias;
    const float* rowScale;    // nullable
    __half* outH;             // exactly one of outH/outF non-null
    float*  outF;
    int ldo;
    bool silu;
    const __half* A2;         // optional second accumulation pass
    const __half* W2;
};

// MW = number of M-warps (4 -> 128-row tile, 2 -> 64-row tile)
template <int MW>
__device__ __forceinline__ void gemm_t(const GemmArgs g) {
    constexpr int NW    = 8 / MW;        // n-warps
    constexpr int WCOLS = 128 / NW;      // cols per warp (16*MW)
    constexpr int NB    = WCOLS / 8;     // 8-col groups per warp (2*MW)
    constexpr int AROWS = MW * 32;

    extern __shared__ char smc[];
    int*   rows_s  = (int*)smc;
    float* scale_s = (float*)(smc + 512);
    const uint32_t sbase = smem_u32(smc);

    const int tid = threadIdx.x;
    const int lane = tid & 31, w = tid >> 5;
    const int mw = w % MW, nw = w / MW;
    const int gg = lane >> 2, cc = lane & 3;
    const int arow = (lane & 7) + ((lane >> 3) & 1) * 8;
    const int kh = (lane >> 4) & 1;

    if (tid < AROWS) {
        bool v = tid < g.valid;
        rows_s[tid]  = g.gather ? (v ? g.gather[tid] : -1) : (v ? tid : -1);
        scale_s[tid] = (g.rowScale && v) ? g.rowScale[tid] : 1.0f;
    }
    __syncthreads();

    float acc[2][NB][4];
#pragma unroll
    for (int i = 0; i < 2; i++)
#pragma unroll
        for (int j = 0; j < NB; j++)
#pragma unroll
            for (int q = 0; q < 4; q++) acc[i][j][q] = 0.0f;

    const int nch = g.K >> 6;
    const int npass = g.A2 ? 2 : 1;

    for (int pass = 0; pass < npass; pass++) {
        const __half* Ap = pass ? g.A2 : g.A;
        const __half* Wp = pass ? g.W2 : g.W;

        const __half* asrc[MW]; uint32_t aoff[MW], asz[MW];
        const __half* bsrc[4];  uint32_t boff[4];
#pragma unroll
        for (int i = 0; i < MW; i++) {
            int idx = tid + i * 256;
            int r = idx >> 3, c = idx & 7;
            int gr = rows_s[r];
            asrc[i] = Ap + (gr >= 0 ? (size_t)gr * g.lda : 0) + c * 8;
            asz[i]  = (gr >= 0) ? 16u : 0u;
            aoff[i] = (uint32_t)(r * PA_B + c * 16);
        }
#pragma unroll
        for (int i = 0; i < 4; i++) {
            int idx = tid + i * 256;
            int k = idx >> 4, bc = idx & 15;
            bsrc[i] = Wp + (size_t)k * g.ldw + g.n0 + bc * 8;
            boff[i] = (uint32_t)(STG_A + k * PB_B + bc * 16);
        }

        auto issue = [&](int chunk, int st) {
            uint32_t sb = sbase + 1024u + (uint32_t)st * STG_BYTES;
            int k0 = chunk << 6;
            size_t bstep = (size_t)k0 * g.ldw;
#pragma unroll
            for (int i = 0; i < MW; i++) cp16(sb + aoff[i], asrc[i] + k0, asz[i]);
#pragma unroll
            for (int i = 0; i < 4; i++) cp16(sb + boff[i], bsrc[i] + bstep, 16u);
        };

        issue(0, 0); CP_COMMIT();
        if (nch > 1) issue(1, 1);
        CP_COMMIT();

        int stcur = 0;
        int stp = (nch > 2) ? 2 : 0;
        for (int c = 0; c < nch; c++) {
            CP_WAIT(1);
            __syncthreads();
            const uint32_t sb = sbase + 1024u + (uint32_t)stcur * STG_BYTES;
            if (++stcur == NSTAGE) stcur = 0;
            if (c + 2 < nch) {
                issue(c + 2, stp);
                if (++stp == NSTAGE) stp = 0;
            }
            CP_COMMIT();
            const uint32_t Ab = sb, Bb = sb + STG_A;
#pragma unroll
            for (int ks = 0; ks < 4; ks++) {
                uint32_t a[2][4], bf[NB][2];
#pragma unroll
                for (int ma = 0; ma < 2; ma++) {
                    uint32_t addr = Ab + (uint32_t)((mw * 32 + ma * 16 + arow) * PA_B + ks * 32 + kh * 16);
                    ldsm_x4(a[ma], addr);
                }
#pragma unroll
                for (int p = 0; p < MW; p++) {
                    uint32_t r4[4];
                    uint32_t addr = Bb + (uint32_t)((ks * 16 + arow) * PB_B + (nw * WCOLS + p * 16 + kh * 8) * 2);
                    ldsm_x4_trans(r4, addr);
                    bf[2 * p][0] = r4[0]; bf[2 * p][1] = r4[1];
                    bf[2 * p + 1][0] = r4[2]; bf[2 * p + 1][1] = r4[3];
                }
#pragma unroll
                for (int ma = 0; ma < 2; ma++)
#pragma unroll
                    for (int nb = 0; nb < NB; nb++)
                        mma_fp16(acc[ma][nb], a[ma], bf[nb][0], bf[nb][1]);
            }
        }
        CP_WAIT(0);
        __syncthreads();
    }

    // direct register epilogue
#pragma unroll
    for (int ma = 0; ma < 2; ma++) {
        int r0 = mw * 32 + ma * 16 + gg, r1 = r0 + 8;
        float s0 = scale_s[r0], s1 = scale_s[r1];
        bool v0 = r0 < g.valid, v1 = r1 < g.valid;
#pragma unroll
        for (int nb = 0; nb < NB; nb++) {
            int n = g.n0 + nw * WCOLS + nb * 8 + cc * 2;
            float bv0 = g.bias[n], bv1 = g.bias[n + 1];
            float f0 = acc[ma][nb][0] + bv0;
            float f1 = acc[ma][nb][1] + bv1;
            float f2 = acc[ma][nb][2] + bv0;
            float f3 = acc[ma][nb][3] + bv1;
            if (g.silu) { f0 = silu_f(f0); f1 = silu_f(f1); f2 = silu_f(f2); f3 = silu_f(f3); }
            if (g.outH) {
                if (v0) {
                    __half2 h = __floats2half2_rn(f0 * s0, f1 * s0);
                    *(__half2*)(g.outH + (size_t)r0 * g.ldo + n) = h;
                }
                if (v1) {
                    __half2 h = __floats2half2_rn(f2 * s1, f3 * s1);
                    *(__half2*)(g.outH + (size_t)r1 * g.ldo + n) = h;
                }
            } else {
                if (v0) *(float2*)(g.outF + (size_t)r0 * g.ldo + n) = make_float2(f0 * s0, f1 * s0);
                if (v1) *(float2*)(g.outF + (size_t)r1 * g.ldo + n) = make_float2(f2 * s1, f3 * s1);
            }
        }
    }
}

// ---------------- GEMM kernels ----------------
__global__ void __launch_bounds__(256, 2) shared_g1_kernel(const float* sb1) {
    int bx = blockIdx.x;            // 512 blocks
    int es = bx >> 8, idx = bx & 255;
    int row0 = (idx & 15) * 128, n0 = (idx >> 4) * 128;
    GemmArgs a;
    a.A = g_x16 + (size_t)row0 * Dm; a.lda = Dm; a.gather = nullptr; a.valid = 128;
    a.W = g_sw116 + (size_t)es * Dm * HSn; a.ldw = HSn; a.n0 = n0;
    a.K = Dm; a.bias = sb1 + (size_t)es * HSn; a.rowScale = nullptr;
    a.outH = g_Hs16 + (size_t)es * Tn * HSn + (size_t)row0 * HSn; a.outF = nullptr; a.ldo = HSn; a.silu = true;
    a.A2 = nullptr; a.W2 = nullptr;
    gemm_t<4>(a);
}
__global__ void __launch_bounds__(256, 2) routed_g1_kernel(const float* b1) {
    int q = blockIdx.x;             // 512 blocks
    int t = q & 255, ny = q >> 8;
    if (t >= g_ntiles) return;
    int e = g_tile_e[t], rb = g_tile_row[t];
    int cnt = g_count[e], off = g_offset[e];
    GemmArgs a;
    a.A = g_x16; a.lda = Dm; a.gather = g_pair_token + off + rb; a.valid = min(128, cnt - rb);
    a.W = g_w116 + (size_t)e * Dm * Hh; a.ldw = Hh; a.n0 = ny * 128;
    a.K = Dm; a.bias = b1 + e * Hh; a.rowScale = nullptr;
    a.outH = g_H16 + (size_t)(off + rb) * Hh; a.outF = nullptr; a.ldo = Hh; a.silu = true;
    a.A2 = nullptr; a.W2 = nullptr;
    gemm_t<4>(a);
}
__global__ void __launch_bounds__(256, 2) routed_g1_64_kernel(const float* b1) {
    int q = blockIdx.x;             // 128 blocks
    int t = q & 63, ny = q >> 6;
    if (t >= g_ntiles64) return;
    int e = g_t64_e[t], rb = g_t64_row[t];
    int cnt = g_count[e], off = g_offset[e];
    GemmArgs a;
    a.A = g_x16; a.lda = Dm; a.gather = g_pair_token + off + rb; a.valid = min(64, cnt - rb);
    a.W = g_w116 + (size_t)e * Dm * Hh; a.ldw = Hh; a.n0 = ny * 128;
    a.K = Dm; a.bias = b1 + e * Hh; a.rowScale = nullptr;
    a.outH = g_H16 + (size_t)(off + rb) * Hh; a.outF = nullptr; a.ldo = Hh; a.silu = true;
    a.A2 = nullptr; a.W2 = nullptr;
    gemm_t<2>(a);
}
__global__ void __launch_bounds__(256, 2) shared_g2_kernel(const float* sb2) {
    int bx = blockIdx.x;            // 128 blocks, es folded
    int row0 = (bx & 15) * 128, n0 = (bx >> 4) * 128;
    GemmArgs a;
    a.A  = g_Hs16 + (size_t)row0 * HSn; a.lda = HSn; a.gather = nullptr; a.valid = 128;
    a.W  = g_sw216; a.ldw = Dm; a.n0 = n0;
    a.A2 = g_Hs16 + (size_t)Tn * HSn + (size_t)row0 * HSn;
    a.W2 = g_sw216 + (size_t)HSn * Dm;
    a.K = HSn; a.bias = sb2; a.rowScale = nullptr;   // es0 bias here; es1 bias added in combine
    a.outH = nullptr; a.outF = g_sharedsum + (size_t)row0 * Dm; a.ldo = Dm; a.silu = false;
    gemm_t<4>(a);
}
__global__ void __launch_bounds__(256, 2) routed_g2_kernel(const float* b2) {
    int q = blockIdx.x;             // 2048 blocks
    int t = q & 255, ny = q >> 8;
    if (t >= g_ntiles) return;
    int e = g_tile_e[t], rb = g_tile_row[t];
    int cnt = g_count[e], off = g_offset[e];
    GemmArgs a;
    a.A = g_H16 + (size_t)(off + rb) * Hh; a.lda = Hh; a.gather = nullptr; a.valid = min(128, cnt - rb);
    a.W = g_w216 + (size_t)e * Hh * Dm; a.ldw = Dm; a.n0 = ny * 128;
    a.K = Hh; a.bias = b2 + (size_t)e * Dm; a.rowScale = g_pair_w + off + rb;
    a.outH = g_pairout16 + (size_t)(off + rb) * Dm; a.outF = nullptr; a.ldo = Dm; a.silu = false;
    a.A2 = nullptr; a.W2 = nullptr;
    gemm_t<4>(a);
}
__global__ void __launch_bounds__(256, 2) routed_g2_64_kernel(const float* b2) {
    int q = blockIdx.x;             // 512 blocks
    int t = q & 63, ny = q >> 6;
    if (t >= g_ntiles64) return;
    int e = g_t64_e[t], rb = g_t64_row[t];
    int cnt = g_count[e], off = g_offset[e];
    GemmArgs a;
    a.A = g_H16 + (size_t)(off + rb) * Hh; a.lda = Hh; a.gather = nullptr; a.valid = min(64, cnt - rb);
    a.W = g_w216 + (size_t)e * Hh * Dm; a.ldw = Dm; a.n0 = ny * 128;
    a.K = Hh; a.bias = b2 + (size_t)e * Dm; a.rowScale = g_pair_w + off + rb;
    a.outH = g_pairout16 + (size_t)(off + rb) * Dm; a.outF = nullptr; a.ldo = Dm; a.silu = false;
    a.A2 = nullptr; a.W2 = nullptr;
    gemm_t<2>(a);
}

// ---------------- fp32 -> fp16 conversion ----------------
__global__ void __launch_bounds__(256) conv_kernel(const float* __restrict__ src, __half* __restrict__ dst, int n4) {
    for (int i = blockIdx.x * 256 + threadIdx.x; i < n4; i += gridDim.x * 256) {
        float4 v = *(const float4*)(src + (size_t)i * 4);
        __half2 h0 = __floats2half2_rn(v.x, v.y);
        __half2 h1 = __floats2half2_rn(v.z, v.w);
        uint32_t u0 = *(uint32_t*)&h0;
        uint32_t u1 = *(uint32_t*)&h1;
        *(uint2*)(dst + (size_t)i * 4) = make_uint2(u0, u1);
    }
}

// ---------------- routing bookkeeping ----------------
__global__ void zero_counts_kernel() {
    if (threadIdx.x < Ne) g_count[threadIdx.x] = 0;
}

__global__ void __launch_bounds__(256) router_kernel(
    const float* __restrict__ x, const float* __restrict__ rw, const float* __restrict__ rb)
{
    __shared__ float xs[64][33];
    __shared__ float ws[64][65];
    __shared__ float lg[32][65];
    int tid = threadIdx.x;
    int tbase = blockIdx.x * 32;
    int e = tid & 63, tg = tid >> 6;
    float acc[8];
#pragma unroll
    for (int i = 0; i < 8; i++) acc[i] = 0.0f;
    for (int d0 = 0; d0 < Dm; d0 += 64) {
#pragma unroll
        for (int q = 0; q < 8; q++) {
            int idx = tid + q * 256; int t = idx >> 6, dd = idx & 63;
            xs[dd][t] = x[(size_t)(tbase + t) * Dm + d0 + dd];
        }
#pragma unroll
        for (int q = 0; q < 16; q++) {
            int idx = tid + q * 256; int dd = idx >> 6, ee = idx & 63;
            ws[dd][ee] = rw[(size_t)(d0 + dd) * Ne + ee];
        }
        __syncthreads();
#pragma unroll
        for (int dd = 0; dd < 64; dd++) {
            float wv = ws[dd][e];
#pragma unroll
            for (int i = 0; i < 8; i++) acc[i] += xs[dd][tg + 4 * i] * wv;
        }
        __syncthreads();
    }
#pragma unroll
    for (int i = 0; i < 8; i++) lg[tg + 4 * i][e] = acc[i] + rb[e];
    __syncthreads();
    if (tid < 32) {
        int t = tid;
        float vals[TOPK]; int idxs[TOPK];
#pragma unroll
        for (int p = 0; p < TOPK; p++) {
            float best = -1e30f; int bi = 0;
            for (int ee = 0; ee < Ne; ee++) {
                float v = lg[t][ee];
                if (v > best) { best = v; bi = ee; }
            }
            vals[p] = best; idxs[p] = bi; lg[t][bi] = -1e30f;
        }
        float m = vals[0], wv[TOPK], s = 0.0f;
#pragma unroll
        for (int p = 0; p < TOPK; p++) { wv[p] = __expf(vals[p] - m); s += wv[p]; }
        float inv = 1.0f / s;
        int gt = tbase + t;
#pragma unroll
        for (int p = 0; p < TOPK; p++) {
            g_topw[gt * TOPK + p] = wv[p] * inv;
            g_topi[gt * TOPK + p] = idxs[p];
            atomicAdd(&g_count[idxs[p]], 1);
        }
    }
}

__global__ void scan_kernel() {
    if (threadIdx.x == 0) {
        int run = 0, nt = 0, nt64 = 0;
        for (int e = 0; e < Ne; e++) {
            g_offset[e] = run; g_cursor[e] = run;
            int c = g_count[e];
            int full = c >> 7, rem = c & 127;
            for (int i = 0; i < full; i++) { g_tile_e[nt] = e; g_tile_row[nt] = i * 128; nt++; }
            if (rem > 64)      { g_tile_e[nt] = e; g_tile_row[nt] = full * 128; nt++; }
            else if (rem > 0)  { g_t64_e[nt64] = e; g_t64_row[nt64] = full * 128; nt64++; }
            run += c;
        }
        g_ntiles = nt;
        g_ntiles64 = nt64;
    }
}

// one thread per (token, slot) pair
__global__ void fill_kernel() {
    int idx = blockIdx.x * 256 + threadIdx.x;
    if (idx < MAXP) {
        int e = g_topi[idx];
        int pos = atomicAdd(&g_cursor[e], 1);
        g_pair_token[pos] = idx >> 3;
        g_pair_w[pos] = g_topw[idx];
        g_slot2pair[idx] = pos;
    }
}

// ---------------- combine (sharedsum fp32 + es1 bias + 8 routed fp16) ----------------
__global__ void __launch_bounds__(256) combine_kernel(float* __restrict__ out, const float* __restrict__ sb2) {
    int t = blockIdx.x, tid = threadIdx.x;
    __shared__ int sp[TOPK];
    if (tid < TOPK) sp[tid] = g_slot2pair[t * TOPK + tid];
    __syncthreads();
    float4 s = *(const float4*)(g_sharedsum + (size_t)t * Dm + tid * 4);
    // es1 bias not yet applied (shared_g2 applied es0 bias only once; es1 pass adds raw GEMM)
    float4 b1v = *(const float4*)(sb2 + (size_t)Dm + tid * 4);
    float acc0 = s.x + b1v.x, acc1 = s.y + b1v.y, acc2 = s.z + b1v.z, acc3 = s.w + b1v.w;
#pragma unroll
    for (int j = 0; j < TOPK; j++) {
        uint2 u = *(const uint2*)(g_pairout16 + (size_t)sp[j] * Dm + tid * 4);
        __half2 h0 = *(__half2*)&u.x, h1 = *(__half2*)&u.y;
        float2 f0 = __half22float2(h0), f1 = __half22float2(h1);
        acc0 += f0.x; acc1 += f0.y; acc2 += f1.x; acc3 += f1.y;
    }
    *(float4*)(out + (size_t)t * Dm + tid * 4) = make_float4(acc0, acc1, acc2, acc3);
}

// ---------------- launch ----------------
extern "C" void kernel_launch(void* const* d_in, const int* in_sizes, int n_in,
                              void* d_out, int out_size)
{
    const float* x   = (const float*)d_in[0];
    const float* rw  = (const float*)d_in[1];
    const float* rb  = (const float*)d_in[2];
    const float* w1  = (const float*)d_in[3];
    const float* b1  = (const float*)d_in[4];
    const float* w2  = (const float*)d_in[5];
    const float* b2  = (const float*)d_in[6];
    const float* sw1 = (const float*)d_in[7];
    const float* sb1 = (const float*)d_in[8];
    const float* sw2 = (const float*)d_in[9];
    const float* sb2 = (const float*)d_in[10];
    float* out = (float*)d_out;

    cudaFuncSetAttribute(shared_g1_kernel,    cudaFuncAttributeMaxDynamicSharedMemorySize, SMEM_DYN);
    cudaFuncSetAttribute(routed_g1_kernel,    cudaFuncAttributeMaxDynamicSharedMemorySize, SMEM_DYN);
    cudaFuncSetAttribute(routed_g1_64_kernel, cudaFuncAttributeMaxDynamicSharedMemorySize, SMEM_DYN);
    cudaFuncSetAttribute(shared_g2_kernel,    cudaFuncAttributeMaxDynamicSharedMemorySize, SMEM_DYN);
    cudaFuncSetAttribute(routed_g2_kernel,    cudaFuncAttributeMaxDynamicSharedMemorySize, SMEM_DYN);
    cudaFuncSetAttribute(routed_g2_64_kernel, cudaFuncAttributeMaxDynamicSharedMemorySize, SMEM_DYN);

    __half* x16  = nullptr; cudaGetSymbolAddress((void**)&x16,  g_x16);
    __half* w116 = nullptr; cudaGetSymbolAddress((void**)&w116, g_w116);
    __half* w216 = nullptr; cudaGetSymbolAddress((void**)&w216, g_w216);
    __half* s116 = nullptr; cudaGetSymbolAddress((void**)&s116, g_sw116);
    __half* s216 = nullptr; cudaGetSymbolAddress((void**)&s216, g_sw216);

    static cudaStream_t sA = nullptr, sB = nullptr, sC = nullptr;
    static cudaEvent_t evRoot = nullptr, evB = nullptr, evC = nullptr, evSG2 = nullptr, evX = nullptr;
    if (!sA) {
        cudaStreamCreateWithFlags(&sA, cudaStreamNonBlocking);
        cudaStreamCreateWithFlags(&sB, cudaStreamNonBlocking);
        cudaStreamCreateWithFlags(&sC, cudaStreamNonBlocking);
        cudaEventCreateWithFlags(&evRoot, cudaEventDisableTiming);
        cudaEventCreateWithFlags(&evB, cudaEventDisableTiming);
        cudaEventCreateWithFlags(&evC, cudaEventDisableTiming);
        cudaEventCreateWithFlags(&evSG2, cudaEventDisableTiming);
        cudaEventCreateWithFlags(&evX, cudaEventDisableTiming);
    }

    // fork
    cudaEventRecord(evRoot, 0);
    cudaStreamWaitEvent(sA, evRoot, 0);
    cudaStreamWaitEvent(sB, evRoot, 0);
    cudaStreamWaitEvent(sC, evRoot, 0);

    // main stream: routing chain
    zero_counts_kernel<<<1, 64>>>();
    router_kernel<<<Tn / 32, 256>>>(x, rw, rb);
    scan_kernel<<<1, 32>>>();
    fill_kernel<<<MAXP / 256, 256>>>();

    // stream B: w1 conversion (gates routed_g1)
    conv_kernel<<<2048, 256, 0, sB>>>(w1, w116, Ne * Dm * Hh / 4);
    cudaEventRecord(evB, sB);

    // stream C: g2 weight conversions
    conv_kernel<<<2048, 256, 0, sC>>>(w2,  w216, Ne * Hh * Dm / 4);
    conv_kernel<<<2048, 256, 0, sC>>>(sw2, s216, ESn * HSn * Dm / 4);
    cudaEventRecord(evC, sC);

    // stream A: shared chain
    conv_kernel<<<1024, 256, 0, sA>>>(x,   x16,  Tn * Dm / 4);
    conv_kernel<<<1024, 256, 0, sA>>>(sw1, s116, ESn * Dm * HSn / 4);
    cudaEventRecord(evX, sA);     // x16 (and sw116) ready
    shared_g1_kernel<<<512, 256, SMEM_DYN, sA>>>(sb1);
    cudaStreamWaitEvent(sA, evC, 0);
    shared_g2_kernel<<<128, 256, SMEM_DYN, sA>>>(sb2);
    cudaEventRecord(evSG2, sA);

    // main: routed chain
    cudaStreamWaitEvent(0, evB, 0);
    cudaStreamWaitEvent(0, evX, 0);
    routed_g1_kernel<<<512, 256, SMEM_DYN>>>(b1);
    routed_g1_64_kernel<<<128, 256, SMEM_DYN>>>(b1);
    cudaStreamWaitEvent(0, evC, 0);
    routed_g2_kernel<<<2048, 256, SMEM_DYN>>>(b2);
    routed_g2_64_kernel<<<512, 256, SMEM_DYN>>>(b2);

    // combine after both chains
    cudaStreamWaitEvent(0, evSG2, 0);
    combine_kernel<<<Tn, 256>>>(out, sb2);
}

// round 17
// speedup vs baseline: 1.0531x; 1.0531x over previous
#include <cuda_runtime.h>
#include <cuda_fp16.h>
#include <cstdint>
#include <math.h>

#define Tn   2048
#define Dm   1024
#define Ne   64
#define TOPK 8
#define Hh   256
#define ESn  2
#define HSn  2048
#define MAXP (Tn * TOPK)
#define MAXTILES 256

// ---------------- static scratch ----------------
__device__ float g_topw[MAXP];
__device__ int   g_topi[MAXP];
__device__ int   g_slot2pair[MAXP];
__device__ int   g_count[Ne];
__device__ int   g_offset[Ne];
__device__ int   g_cursor[Ne];
__device__ int   g_pair_token[MAXP];
__device__ float g_pair_w[MAXP];
__device__ int   g_ntiles;
__device__ int   g_tile_e[MAXTILES];
__device__ int   g_tile_row[MAXTILES];
__device__ int   g_ntiles64;
__device__ int   g_t64_e[Ne];
__device__ int   g_t64_row[Ne];
__device__ __half g_pairout16[(size_t)MAXP * Dm];
__device__ float  g_sharedsum[(size_t)Tn * Dm];
__device__ __half g_H16[(size_t)MAXP * Hh];
__device__ __half g_Hs16[(size_t)ESn * Tn * HSn];
// fp16 operand copies
__device__ __half g_x16[(size_t)Tn * Dm];
__device__ __half g_w116[(size_t)Ne * Dm * Hh];
__device__ __half g_w216[(size_t)Ne * Hh * Dm];
__device__ __half g_sw116[(size_t)ESn * Dm * HSn];
__device__ __half g_sw216[(size_t)ESn * HSn * Dm];

__device__ __forceinline__ uint32_t smem_u32(const void* p) {
    uint32_t a;
    asm("{ .reg .u64 t; cvta.to.shared.u64 t, %1; cvt.u32.u64 %0, t; }" : "=r"(a) : "l"(p));
    return a;
}
__device__ __forceinline__ float silu_f(float c) { return c / (1.0f + __expf(-c)); }

__device__ __forceinline__ void ldsm_x4(uint32_t* r, uint32_t addr) {
    asm volatile("ldmatrix.sync.aligned.m8n8.x4.shared.b16 {%0,%1,%2,%3}, [%4];"
        : "=r"(r[0]), "=r"(r[1]), "=r"(r[2]), "=r"(r[3]) : "r"(addr));
}
__device__ __forceinline__ void ldsm_x4_trans(uint32_t* r, uint32_t addr) {
    asm volatile("ldmatrix.sync.aligned.m8n8.x4.trans.shared.b16 {%0,%1,%2,%3}, [%4];"
        : "=r"(r[0]), "=r"(r[1]), "=r"(r[2]), "=r"(r[3]) : "r"(addr));
}
__device__ __forceinline__ void mma_fp16(float* d, const uint32_t* a, uint32_t b0, uint32_t b1) {
    asm volatile(
        "mma.sync.aligned.m16n8k16.row.col.f32.f16.f16.f32 "
        "{%0,%1,%2,%3}, {%4,%5,%6,%7}, {%8,%9}, {%0,%1,%2,%3};"
        : "+f"(d[0]), "+f"(d[1]), "+f"(d[2]), "+f"(d[3])
        : "r"(a[0]), "r"(a[1]), "r"(a[2]), "r"(a[3]), "r"(b0), "r"(b1));
}
__device__ __forceinline__ void cp16(uint32_t dst, const void* src, uint32_t sz) {
    asm volatile("cp.async.cg.shared.global [%0], [%1], 16, %2;"
        :: "r"(dst), "l"(src), "r"(sz) : "memory");
}
#define CP_COMMIT() asm volatile("cp.async.commit_group;" ::: "memory")
#define CP_WAIT(n)  asm volatile("cp.async.wait_group %0;" :: "n"(n) : "memory")

// pipeline geometry: K-chunk = 64
#define NSTAGE 3
#define PA_B 144
#define PB_B 272
#define STG_A 18432
#define STG_B 17408
#define STG_BYTES (STG_A + STG_B)
#define SMEM_DYN (1024 + NSTAGE * STG_BYTES)   // 108544

struct GemmArgs {
    const __half* A; int lda; const int* gather; int valid;
    const __half* W; int ldw; int n0;
    int K;
    const float* bias;
    const float* rowScale;    // nullable
    __half* outH;             // exactly one of outH/outF non-null
    float*  outF;
    int ldo;
    bool silu;
    const __half* A2;         // optional second accumulation pass
    const __half* W2;
};

// MW = number of M-warps (4 -> 128-row tile, 2 -> 64-row tile)
template <int MW>
__device__ __forceinline__ void gemm_t(const GemmArgs g) {
    constexpr int NW    = 8 / MW;
    constexpr int WCOLS = 128 / NW;
    constexpr int NB    = WCOLS / 8;
    constexpr int AROWS = MW * 32;

    extern __shared__ char smc[];
    int*   rows_s  = (int*)smc;
    float* scale_s = (float*)(smc + 512);
    const uint32_t sbase = smem_u32(smc);

    const int tid = threadIdx.x;
    const int lane = tid & 31, w = tid >> 5;
    const int mw = w % MW, nw = w / MW;
    const int gg = lane >> 2, cc = lane & 3;
    const int arow = (lane & 7) + ((lane >> 3) & 1) * 8;
    const int kh = (lane >> 4) & 1;

    if (tid < AROWS) {
        bool v = tid < g.valid;
        rows_s[tid]  = g.gather ? (v ? g.gather[tid] : -1) : (v ? tid : -1);
        scale_s[tid] = (g.rowScale && v) ? g.rowScale[tid] : 1.0f;
    }
    __syncthreads();

    float acc[2][NB][4];
#pragma unroll
    for (int i = 0; i < 2; i++)
#pragma unroll
        for (int j = 0; j < NB; j++)
#pragma unroll
            for (int q = 0; q < 4; q++) acc[i][j][q] = 0.0f;

    const int nch = g.K >> 6;
    const int npass = g.A2 ? 2 : 1;

    for (int pass = 0; pass < npass; pass++) {
        const __half* Ap = pass ? g.A2 : g.A;
        const __half* Wp = pass ? g.W2 : g.W;

        const __half* asrc[MW]; uint32_t aoff[MW], asz[MW];
        const __half* bsrc[4];  uint32_t boff[4];
#pragma unroll
        for (int i = 0; i < MW; i++) {
            int idx = tid + i * 256;
            int r = idx >> 3, c = idx & 7;
            int gr = rows_s[r];
            asrc[i] = Ap + (gr >= 0 ? (size_t)gr * g.lda : 0) + c * 8;
            asz[i]  = (gr >= 0) ? 16u : 0u;
            aoff[i] = (uint32_t)(r * PA_B + c * 16);
        }
#pragma unroll
        for (int i = 0; i < 4; i++) {
            int idx = tid + i * 256;
            int k = idx >> 4, bc = idx & 15;
            bsrc[i] = Wp + (size_t)k * g.ldw + g.n0 + bc * 8;
            boff[i] = (uint32_t)(STG_A + k * PB_B + bc * 16);
        }

        auto issue = [&](int chunk, int st) {
            uint32_t sb = sbase + 1024u + (uint32_t)st * STG_BYTES;
            int k0 = chunk << 6;
            size_t bstep = (size_t)k0 * g.ldw;
#pragma unroll
            for (int i = 0; i < MW; i++) cp16(sb + aoff[i], asrc[i] + k0, asz[i]);
#pragma unroll
            for (int i = 0; i < 4; i++) cp16(sb + boff[i], bsrc[i] + bstep, 16u);
        };

        issue(0, 0); CP_COMMIT();
        if (nch > 1) issue(1, 1);
        CP_COMMIT();

        int stcur = 0;
        int stp = (nch > 2) ? 2 : 0;
        for (int c = 0; c < nch; c++) {
            CP_WAIT(1);
            __syncthreads();
            const uint32_t sb = sbase + 1024u + (uint32_t)stcur * STG_BYTES;
            if (++stcur == NSTAGE) stcur = 0;
            if (c + 2 < nch) {
                issue(c + 2, stp);
                if (++stp == NSTAGE) stp = 0;
            }
            CP_COMMIT();
            const uint32_t Ab = sb, Bb = sb + STG_A;
#pragma unroll
            for (int ks = 0; ks < 4; ks++) {
                uint32_t a[2][4], bf[NB][2];
#pragma unroll
                for (int ma = 0; ma < 2; ma++) {
                    uint32_t addr = Ab + (uint32_t)((mw * 32 + ma * 16 + arow) * PA_B + ks * 32 + kh * 16);
                    ldsm_x4(a[ma], addr);
                }
#pragma unroll
                for (int p = 0; p < MW; p++) {
                    uint32_t r4[4];
                    uint32_t addr = Bb + (uint32_t)((ks * 16 + arow) * PB_B + (nw * WCOLS + p * 16 + kh * 8) * 2);
                    ldsm_x4_trans(r4, addr);
                    bf[2 * p][0] = r4[0]; bf[2 * p][1] = r4[1];
                    bf[2 * p + 1][0] = r4[2]; bf[2 * p + 1][1] = r4[3];
                }
#pragma unroll
                for (int ma = 0; ma < 2; ma++)
#pragma unroll
                    for (int nb = 0; nb < NB; nb++)
                        mma_fp16(acc[ma][nb], a[ma], bf[nb][0], bf[nb][1]);
            }
        }
        CP_WAIT(0);
        __syncthreads();
    }

    // direct register epilogue
#pragma unroll
    for (int ma = 0; ma < 2; ma++) {
        int r0 = mw * 32 + ma * 16 + gg, r1 = r0 + 8;
        float s0 = scale_s[r0], s1 = scale_s[r1];
        bool v0 = r0 < g.valid, v1 = r1 < g.valid;
#pragma unroll
        for (int nb = 0; nb < NB; nb++) {
            int n = g.n0 + nw * WCOLS + nb * 8 + cc * 2;
            float bv0 = g.bias[n], bv1 = g.bias[n + 1];
            float f0 = acc[ma][nb][0] + bv0;
            float f1 = acc[ma][nb][1] + bv1;
            float f2 = acc[ma][nb][2] + bv0;
            float f3 = acc[ma][nb][3] + bv1;
            if (g.silu) { f0 = silu_f(f0); f1 = silu_f(f1); f2 = silu_f(f2); f3 = silu_f(f3); }
            if (g.outH) {
                if (v0) {
                    __half2 h = __floats2half2_rn(f0 * s0, f1 * s0);
                    *(__half2*)(g.outH + (size_t)r0 * g.ldo + n) = h;
                }
                if (v1) {
                    __half2 h = __floats2half2_rn(f2 * s1, f3 * s1);
                    *(__half2*)(g.outH + (size_t)r1 * g.ldo + n) = h;
                }
            } else {
                if (v0) *(float2*)(g.outF + (size_t)r0 * g.ldo + n) = make_float2(f0 * s0, f1 * s0);
                if (v1) *(float2*)(g.outF + (size_t)r1 * g.ldo + n) = make_float2(f2 * s1, f3 * s1);
            }
        }
    }
}

// ---------------- GEMM kernels ----------------
__global__ void __launch_bounds__(256, 2) shared_g1_kernel(const float* sb1) {
    int bx = blockIdx.x;            // 512 blocks
    int es = bx >> 8, idx = bx & 255;
    int row0 = (idx & 15) * 128, n0 = (idx >> 4) * 128;
    GemmArgs a;
    a.A = g_x16 + (size_t)row0 * Dm; a.lda = Dm; a.gather = nullptr; a.valid = 128;
    a.W = g_sw116 + (size_t)es * Dm * HSn; a.ldw = HSn; a.n0 = n0;
    a.K = Dm; a.bias = sb1 + (size_t)es * HSn; a.rowScale = nullptr;
    a.outH = g_Hs16 + (size_t)es * Tn * HSn + (size_t)row0 * HSn; a.outF = nullptr; a.ldo = HSn; a.silu = true;
    a.A2 = nullptr; a.W2 = nullptr;
    gemm_t<4>(a);
}
__global__ void __launch_bounds__(256, 2) routed_g1_kernel(const float* b1) {
    int q = blockIdx.x;             // 512 blocks
    int t = q & 255, ny = q >> 8;
    if (t >= g_ntiles) return;
    int e = g_tile_e[t], rb = g_tile_row[t];
    int cnt = g_count[e], off = g_offset[e];
    GemmArgs a;
    a.A = g_x16; a.lda = Dm; a.gather = g_pair_token + off + rb; a.valid = min(128, cnt - rb);
    a.W = g_w116 + (size_t)e * Dm * Hh; a.ldw = Hh; a.n0 = ny * 128;
    a.K = Dm; a.bias = b1 + e * Hh; a.rowScale = nullptr;
    a.outH = g_H16 + (size_t)(off + rb) * Hh; a.outF = nullptr; a.ldo = Hh; a.silu = true;
    a.A2 = nullptr; a.W2 = nullptr;
    gemm_t<4>(a);
}
__global__ void __launch_bounds__(256, 2) routed_g1_64_kernel(const float* b1) {
    int q = blockIdx.x;             // 128 blocks
    int t = q & 63, ny = q >> 6;
    if (t >= g_ntiles64) return;
    int e = g_t64_e[t], rb = g_t64_row[t];
    int cnt = g_count[e], off = g_offset[e];
    GemmArgs a;
    a.A = g_x16; a.lda = Dm; a.gather = g_pair_token + off + rb; a.valid = min(64, cnt - rb);
    a.W = g_w116 + (size_t)e * Dm * Hh; a.ldw = Hh; a.n0 = ny * 128;
    a.K = Dm; a.bias = b1 + e * Hh; a.rowScale = nullptr;
    a.outH = g_H16 + (size_t)(off + rb) * Hh; a.outF = nullptr; a.ldo = Hh; a.silu = true;
    a.A2 = nullptr; a.W2 = nullptr;
    gemm_t<2>(a);
}
__global__ void __launch_bounds__(256, 2) shared_g2_kernel(const float* sb2) {
    int bx = blockIdx.x;            // 128 blocks, es folded
    int row0 = (bx & 15) * 128, n0 = (bx >> 4) * 128;
    GemmArgs a;
    a.A  = g_Hs16 + (size_t)row0 * HSn; a.lda = HSn; a.gather = nullptr; a.valid = 128;
    a.W  = g_sw216; a.ldw = Dm; a.n0 = n0;
    a.A2 = g_Hs16 + (size_t)Tn * HSn + (size_t)row0 * HSn;
    a.W2 = g_sw216 + (size_t)HSn * Dm;
    a.K = HSn; a.bias = sb2; a.rowScale = nullptr;   // es0 bias; es1 bias added in combine
    a.outH = nullptr; a.outF = g_sharedsum + (size_t)row0 * Dm; a.ldo = Dm; a.silu = false;
    gemm_t<4>(a);
}
__global__ void __launch_bounds__(256, 2) routed_g2_kernel(const float* b2) {
    int q = blockIdx.x;             // 2048 blocks
    int t = q & 255, ny = q >> 8;
    if (t >= g_ntiles) return;
    int e = g_tile_e[t], rb = g_tile_row[t];
    int cnt = g_count[e], off = g_offset[e];
    GemmArgs a;
    a.A = g_H16 + (size_t)(off + rb) * Hh; a.lda = Hh; a.gather = nullptr; a.valid = min(128, cnt - rb);
    a.W = g_w216 + (size_t)e * Hh * Dm; a.ldw = Dm; a.n0 = ny * 128;
    a.K = Hh; a.bias = b2 + (size_t)e * Dm; a.rowScale = g_pair_w + off + rb;
    a.outH = g_pairout16 + (size_t)(off + rb) * Dm; a.outF = nullptr; a.ldo = Dm; a.silu = false;
    a.A2 = nullptr; a.W2 = nullptr;
    gemm_t<4>(a);
}
__global__ void __launch_bounds__(256, 2) routed_g2_64_kernel(const float* b2) {
    int q = blockIdx.x;             // 512 blocks
    int t = q & 63, ny = q >> 6;
    if (t >= g_ntiles64) return;
    int e = g_t64_e[t], rb = g_t64_row[t];
    int cnt = g_count[e], off = g_offset[e];
    GemmArgs a;
    a.A = g_H16 + (size_t)(off + rb) * Hh; a.lda = Hh; a.gather = nullptr; a.valid = min(64, cnt - rb);
    a.W = g_w216 + (size_t)e * Hh * Dm; a.ldw = Dm; a.n0 = ny * 128;
    a.K = Hh; a.bias = b2 + (size_t)e * Dm; a.rowScale = g_pair_w + off + rb;
    a.outH = g_pairout16 + (size_t)(off + rb) * Dm; a.outF = nullptr; a.ldo = Dm; a.silu = false;
    a.A2 = nullptr; a.W2 = nullptr;
    gemm_t<2>(a);
}

// ---------------- fp32 -> fp16 conversion ----------------
__global__ void __launch_bounds__(256) conv_kernel(const float* __restrict__ src, __half* __restrict__ dst, int n4) {
    for (int i = blockIdx.x * 256 + threadIdx.x; i < n4; i += gridDim.x * 256) {
        float4 v = *(const float4*)(src + (size_t)i * 4);
        __half2 h0 = __floats2half2_rn(v.x, v.y);
        __half2 h1 = __floats2half2_rn(v.z, v.w);
        uint32_t u0 = *(uint32_t*)&h0;
        uint32_t u1 = *(uint32_t*)&h1;
        *(uint2*)(dst + (size_t)i * 4) = make_uint2(u0, u1);
    }
}

// ---------------- routing bookkeeping ----------------
__global__ void zero_counts_kernel() {
    if (threadIdx.x < Ne) g_count[threadIdx.x] = 0;
}

__global__ void __launch_bounds__(256) router_kernel(
    const float* __restrict__ x, const float* __restrict__ rw, const float* __restrict__ rb)
{
    __shared__ float xs[64][33];
    __shared__ float ws[64][65];
    __shared__ float lg[32][65];
    int tid = threadIdx.x;
    int tbase = blockIdx.x * 32;
    int e = tid & 63, tg = tid >> 6;
    float acc[8];
#pragma unroll
    for (int i = 0; i < 8; i++) acc[i] = 0.0f;
    for (int d0 = 0; d0 < Dm; d0 += 64) {
#pragma unroll
        for (int q = 0; q < 8; q++) {
            int idx = tid + q * 256; int t = idx >> 6, dd = idx & 63;
            xs[dd][t] = x[(size_t)(tbase + t) * Dm + d0 + dd];
        }
#pragma unroll
        for (int q = 0; q < 16; q++) {
            int idx = tid + q * 256; int dd = idx >> 6, ee = idx & 63;
            ws[dd][ee] = rw[(size_t)(d0 + dd) * Ne + ee];
        }
        __syncthreads();
#pragma unroll
        for (int dd = 0; dd < 64; dd++) {
            float wv = ws[dd][e];
#pragma unroll
            for (int i = 0; i < 8; i++) acc[i] += xs[dd][tg + 4 * i] * wv;
        }
        __syncthreads();
    }
#pragma unroll
    for (int i = 0; i < 8; i++) lg[tg + 4 * i][e] = acc[i] + rb[e];
    __syncthreads();
    if (tid < 32) {
        int t = tid;
        float vals[TOPK]; int idxs[TOPK];
#pragma unroll
        for (int p = 0; p < TOPK; p++) {
            float best = -1e30f; int bi = 0;
            for (int ee = 0; ee < Ne; ee++) {
                float v = lg[t][ee];
                if (v > best) { best = v; bi = ee; }
            }
            vals[p] = best; idxs[p] = bi; lg[t][bi] = -1e30f;
        }
        float m = vals[0], wv[TOPK], s = 0.0f;
#pragma unroll
        for (int p = 0; p < TOPK; p++) { wv[p] = __expf(vals[p] - m); s += wv[p]; }
        float inv = 1.0f / s;
        int gt = tbase + t;
#pragma unroll
        for (int p = 0; p < TOPK; p++) {
            g_topw[gt * TOPK + p] = wv[p] * inv;
            g_topi[gt * TOPK + p] = idxs[p];
            atomicAdd(&g_count[idxs[p]], 1);
        }
    }
}

__global__ void scan_kernel() {
    if (threadIdx.x == 0) {
        int run = 0, nt = 0, nt64 = 0;
        for (int e = 0; e < Ne; e++) {
            g_offset[e] = run; g_cursor[e] = run;
            int c = g_count[e];
            int full = c >> 7, rem = c & 127;
            for (int i = 0; i < full; i++) { g_tile_e[nt] = e; g_tile_row[nt] = i * 128; nt++; }
            if (rem > 64)      { g_tile_e[nt] = e; g_tile_row[nt] = full * 128; nt++; }
            else if (rem > 0)  { g_t64_e[nt64] = e; g_t64_row[nt64] = full * 128; nt64++; }
            run += c;
        }
        g_ntiles = nt;
        g_ntiles64 = nt64;
    }
}

// one thread per (token, slot) pair
__global__ void fill_kernel() {
    int idx = blockIdx.x * 256 + threadIdx.x;
    if (idx < MAXP) {
        int e = g_topi[idx];
        int pos = atomicAdd(&g_cursor[e], 1);
        g_pair_token[pos] = idx >> 3;
        g_pair_w[pos] = g_topw[idx];
        g_slot2pair[idx] = pos;
    }
}

// ---------------- combine (sharedsum fp32 + es1 bias + 8 routed fp16) ----------------
__global__ void __launch_bounds__(256) combine_kernel(float* __restrict__ out, const float* __restrict__ sb2) {
    int t = blockIdx.x, tid = threadIdx.x;
    __shared__ int sp[TOPK];
    if (tid < TOPK) sp[tid] = g_slot2pair[t * TOPK + tid];
    __syncthreads();
    float4 s = *(const float4*)(g_sharedsum + (size_t)t * Dm + tid * 4);
    float4 b1v = *(const float4*)(sb2 + (size_t)Dm + tid * 4);
    float acc0 = s.x + b1v.x, acc1 = s.y + b1v.y, acc2 = s.z + b1v.z, acc3 = s.w + b1v.w;
#pragma unroll
    for (int j = 0; j < TOPK; j++) {
        uint2 u = *(const uint2*)(g_pairout16 + (size_t)sp[j] * Dm + tid * 4);
        __half2 h0 = *(__half2*)&u.x, h1 = *(__half2*)&u.y;
        float2 f0 = __half22float2(h0), f1 = __half22float2(h1);
        acc0 += f0.x; acc1 += f0.y; acc2 += f1.x; acc3 += f1.y;
    }
    *(float4*)(out + (size_t)t * Dm + tid * 4) = make_float4(acc0, acc1, acc2, acc3);
}

// ---------------- launch ----------------
extern "C" void kernel_launch(void* const* d_in, const int* in_sizes, int n_in,
                              void* d_out, int out_size)
{
    const float* x   = (const float*)d_in[0];
    const float* rw  = (const float*)d_in[1];
    const float* rb  = (const float*)d_in[2];
    const float* w1  = (const float*)d_in[3];
    const float* b1  = (const float*)d_in[4];
    const float* w2  = (const float*)d_in[5];
    const float* b2  = (const float*)d_in[6];
    const float* sw1 = (const float*)d_in[7];
    const float* sb1 = (const float*)d_in[8];
    const float* sw2 = (const float*)d_in[9];
    const float* sb2 = (const float*)d_in[10];
    float* out = (float*)d_out;

    cudaFuncSetAttribute(shared_g1_kernel,    cudaFuncAttributeMaxDynamicSharedMemorySize, SMEM_DYN);
    cudaFuncSetAttribute(routed_g1_kernel,    cudaFuncAttributeMaxDynamicSharedMemorySize, SMEM_DYN);
    cudaFuncSetAttribute(routed_g1_64_kernel, cudaFuncAttributeMaxDynamicSharedMemorySize, SMEM_DYN);
    cudaFuncSetAttribute(shared_g2_kernel,    cudaFuncAttributeMaxDynamicSharedMemorySize, SMEM_DYN);
    cudaFuncSetAttribute(routed_g2_kernel,    cudaFuncAttributeMaxDynamicSharedMemorySize, SMEM_DYN);
    cudaFuncSetAttribute(routed_g2_64_kernel, cudaFuncAttributeMaxDynamicSharedMemorySize, SMEM_DYN);

    __half* x16  = nullptr; cudaGetSymbolAddress((void**)&x16,  g_x16);
    __half* w116 = nullptr; cudaGetSymbolAddress((void**)&w116, g_w116);
    __half* w216 = nullptr; cudaGetSymbolAddress((void**)&w216, g_w216);
    __half* s116 = nullptr; cudaGetSymbolAddress((void**)&s116, g_sw116);
    __half* s216 = nullptr; cudaGetSymbolAddress((void**)&s216, g_sw216);

    static cudaStream_t sA = nullptr, sB = nullptr, sC = nullptr;
    static cudaEvent_t evRoot = nullptr, evB = nullptr, evC = nullptr, evSG2 = nullptr,
                       evX = nullptr, evFill = nullptr, evR64 = nullptr;
    if (!sA) {
        cudaStreamCreateWithFlags(&sA, cudaStreamNonBlocking);
        cudaStreamCreateWithFlags(&sB, cudaStreamNonBlocking);
        cudaStreamCreateWithFlags(&sC, cudaStreamNonBlocking);
        cudaEventCreateWithFlags(&evRoot, cudaEventDisableTiming);
        cudaEventCreateWithFlags(&evB, cudaEventDisableTiming);
        cudaEventCreateWithFlags(&evC, cudaEventDisableTiming);
        cudaEventCreateWithFlags(&evSG2, cudaEventDisableTiming);
        cudaEventCreateWithFlags(&evX, cudaEventDisableTiming);
        cudaEventCreateWithFlags(&evFill, cudaEventDisableTiming);
        cudaEventCreateWithFlags(&evR64, cudaEventDisableTiming);
    }

    // fork
    cudaEventRecord(evRoot, 0);
    cudaStreamWaitEvent(sA, evRoot, 0);
    cudaStreamWaitEvent(sB, evRoot, 0);
    cudaStreamWaitEvent(sC, evRoot, 0);

    // main stream: routing chain
    zero_counts_kernel<<<1, 64>>>();
    router_kernel<<<Tn / 32, 256>>>(x, rw, rb);
    scan_kernel<<<1, 32>>>();
    fill_kernel<<<MAXP / 256, 256>>>();
    cudaEventRecord(evFill, 0);

    // stream B: w1 conversion, then the independent 64-row routed chain
    conv_kernel<<<2048, 256, 0, sB>>>(w1, w116, Ne * Dm * Hh / 4);
    cudaEventRecord(evB, sB);

    // stream C: g2 weight conversions
    conv_kernel<<<2048, 256, 0, sC>>>(w2,  w216, Ne * Hh * Dm / 4);
    conv_kernel<<<2048, 256, 0, sC>>>(sw2, s216, ESn * HSn * Dm / 4);
    cudaEventRecord(evC, sC);

    // stream A: shared chain
    conv_kernel<<<1024, 256, 0, sA>>>(x,   x16,  Tn * Dm / 4);
    conv_kernel<<<1024, 256, 0, sA>>>(sw1, s116, ESn * Dm * HSn / 4);
    cudaEventRecord(evX, sA);
    shared_g1_kernel<<<512, 256, SMEM_DYN, sA>>>(sb1);
    cudaStreamWaitEvent(sA, evC, 0);
    shared_g2_kernel<<<128, 256, SMEM_DYN, sA>>>(sb2);
    cudaEventRecord(evSG2, sA);

    // stream B continues: 64-row routed chain (independent of the 128-row chain)
    cudaStreamWaitEvent(sB, evX, 0);
    cudaStreamWaitEvent(sB, evFill, 0);
    routed_g1_64_kernel<<<128, 256, SMEM_DYN, sB>>>(b1);
    cudaStreamWaitEvent(sB, evC, 0);
    routed_g2_64_kernel<<<512, 256, SMEM_DYN, sB>>>(b2);
    cudaEventRecord(evR64, sB);

    // main: 128-row routed chain
    cudaStreamWaitEvent(0, evB, 0);
    cudaStreamWaitEvent(0, evX, 0);
    routed_g1_kernel<<<512, 256, SMEM_DYN>>>(b1);
    cudaStreamWaitEvent(0, evC, 0);
    routed_g2_kernel<<<2048, 256, SMEM_DYN>>>(b2);

    // combine after all chains
    cudaStreamWaitEvent(0, evSG2, 0);
    cudaStreamWaitEvent(0, evR64, 0);
    combine_kernel<<<Tn, 256>>>(out, sb2);
}